// round 3
// baseline (speedup 1.0000x reference)
#include <cuda_runtime.h>
#include <cstdint>

// ============================================================================
// ConvAConnect: per-sample perturbed 3x3 SAME conv, B=32 H=W=64 Cin=128 F=256
// Implicit GEMM per sample: [4096 x 1152] x [1152 x 256], tf32 mma.sync.
// NOTE: harness PTX target is compute_103 (no 'a') -> tcgen05/TMA unavailable.
// ============================================================================
static constexpr int BATCH = 32;
static constexpr int CIN   = 128;
static constexpr int FOUT  = 256;
static constexpr int NK8   = 144;   // K=1152 / 8
static constexpr int NCHUNK = 36;   // K / 32

// Per-sample weights, tf32-rounded, laid out in exact mma.sync B-fragment order:
// addr = ((b*144 + k8)*4 + wn)*512 + lane*16 + j*2 + slot   (floats)
//   wn = f>>6 (warp N quarter), j = (f>>3)&7 (n-tile), lane = (f&7)*4 + (k&3),
//   slot = (k>>2)&1.  Per (k8,wn,lane): 16 consecutive floats = 4x LDG.128.
__device__ __align__(256) float g_wfrag[(size_t)BATCH * NK8 * 2048];

__device__ __forceinline__ uint32_t smem_u32(const void* p) {
    uint32_t a;
    asm("{ .reg .u64 t; cvta.to.shared.u64 t, %1; cvt.u32.u64 %0, t; }" : "=r"(a) : "l"(p));
    return a;
}
__device__ __forceinline__ uint32_t to_tf32(float x) {
    uint32_t u;
    asm("cvt.rna.tf32.f32 %0, %1;" : "=r"(u) : "f"(x));
    return u;
}

// ============================================================================
// Prep: g_wfrag[b][k8][...] = frag_order(tf32(W * Werr[b]))
// One block per (b, pos). Coalesced gmem reads/writes via 8KB smem staging.
// ============================================================================
__global__ void __launch_bounds__(256) prep_wfrag(const float* __restrict__ W,
                                                  const float* __restrict__ Werr) {
    __shared__ float4 st4[512];                   // 2048 floats = one k8 slab
    uint32_t* st = (uint32_t*)st4;
    int blk = blockIdx.x;
    int b = blk / 9, pos = blk % 9;
    int f = threadIdx.x;                          // 0..255
    const float* wb = W    + (size_t)pos * CIN * FOUT + f;
    const float* eb = Werr + (size_t)(b * 9 + pos) * CIN * FOUT + f;
    int wn = f >> 6, j = (f >> 3) & 7;

    for (int cb = 0; cb < 16; cb++) {             // 16 k8 blocks per pos
        __syncthreads();
#pragma unroll
        for (int ci = 0; ci < 8; ci++) {
            int c = cb * 8 + ci;
            float v = wb[(size_t)c * FOUT] * eb[(size_t)c * FOUT];
            int lane = (f & 7) * 4 + (ci & 3);
            st[wn * 512 + lane * 16 + j * 2 + (ci >> 2)] = to_tf32(v);
        }
        __syncthreads();
        int g = pos * 16 + cb;
        float4* dst = (float4*)(g_wfrag + (size_t)(b * NK8 + g) * 2048);
        dst[f * 2]     = st4[f * 2];
        dst[f * 2 + 1] = st4[f * 2 + 1];
    }
}

// ============================================================================
// Main: 1024 CTAs = 32 samples x 32 M-blocks (128 pixels = 2 image rows each).
// 256 threads, 8 warps: wm = wid&1 (M half), wn = wid>>1 (N quarter).
// Warp tile 64x64, acc in registers. A: 2-stage cp.async smem pipeline.
// B: fragment-ordered LDG.128 from L2 with one-k8 register double buffer.
// ============================================================================
__global__ void __launch_bounds__(256, 1)
conv_main(const float* __restrict__ X, const float* __restrict__ bias,
          const float* __restrict__ Berr, float* __restrict__ out) {
    __shared__ float4 sAbuf[2048];   // 32KB: 2 stages x (128 rows x 128B)
    __shared__ float sMB[256];
    const uint32_t sA = smem_u32(sAbuf);

    const int t = threadIdx.x, l = t & 31, wid = t >> 5;
    const int b = blockIdx.x >> 5, mb = blockIdx.x & 31;
    const int wm = wid & 1, wn = wid >> 1;

    sMB[t] = bias[t] * Berr[b * FOUT + t];

    // ---- A producer mapping: thread t covers row t/2, 4 x 16B segs ----
    const int arow = t >> 1;
    const uint32_t aseg0 = (uint32_t)((t & 1) * 4);

    auto issueA = [&](int s, int stage) {
        int pos = s >> 2, cb = s & 3;
        int kh = pos / 3, kw = pos % 3;
        int y = mb * 2 + (arow >> 6) + kh - 1;
        int x = (arow & 63) + kw - 1;
        bool valid = ((unsigned)y < 64u) && ((unsigned)x < 64u);
        const float* src = X + (((size_t)b * 64 + (valid ? y : 0)) * 64 +
                                (valid ? x : 0)) * CIN + cb * 32;
        int sz = valid ? 16 : 0;
        uint32_t dbase = sA + (uint32_t)stage * 16384u + (uint32_t)arow * 128u;
        uint32_t sw = (uint32_t)((arow & 7) << 4);
#pragma unroll
        for (int jj = 0; jj < 4; jj++) {
            uint32_t seg = aseg0 + (uint32_t)jj;
            uint32_t d = dbase + ((seg * 16u) ^ sw);
            asm volatile("cp.async.cg.shared.global [%0], [%1], 16, %2;"
                         :: "r"(d), "l"(src + seg * 4), "r"(sz) : "memory");
        }
        asm volatile("cp.async.commit_group;" ::: "memory");
    };

    // ---- B fragment base pointer (float4 units) ----
    const float4* bp = (const float4*)g_wfrag +
                       (size_t)b * NK8 * 512 + wn * 128 + l * 4;

    float acc[4][8][4];
#pragma unroll
    for (int mt = 0; mt < 4; mt++)
#pragma unroll
        for (int nt = 0; nt < 8; nt++)
#pragma unroll
            for (int q = 0; q < 4; q++) acc[mt][nt][q] = 0.f;

    // Prologue
    issueA(0, 0);
    float4 bf[2][4];
#pragma unroll
    for (int q = 0; q < 4; q++) bf[0][q] = bp[q];   // g = 0

    for (int s = 0; s < NCHUNK; s++) {
        asm volatile("cp.async.wait_group 0;" ::: "memory");
        __syncthreads();
        if (s + 1 < NCHUNK) issueA(s + 1, (s + 1) & 1);
        const uint32_t stb = sA + (uint32_t)(s & 1) * 16384u;

#pragma unroll
        for (int kk = 0; kk < 4; kk++) {
            int g = s * 4 + kk;
            int gn = (g + 1 < NK8) ? g + 1 : g;
            // prefetch next k8 B fragments
            float4* nb = bf[(kk + 1) & 1];
#pragma unroll
            for (int q = 0; q < 4; q++) nb[q] = bp[(size_t)gn * 512 + q];

            // A fragments (conflict-free swizzled LDS.32) + tf32 round
            uint32_t a[4][4];
            const uint32_t kb0 = (uint32_t)((kk * 8 + (l & 3)) * 4);
#pragma unroll
            for (int mt = 0; mt < 4; mt++) {
                int r = wm * 64 + mt * 16 + (l >> 2);
                uint32_t sw = (uint32_t)((r & 7) << 4);
                uint32_t base = stb + (uint32_t)r * 128u;
                uint32_t ad0 = base + (kb0 ^ sw);
                uint32_t ad2 = base + ((kb0 + 16u) ^ sw);
                float f0, f1, f2, f3;
                asm volatile("ld.shared.f32 %0, [%1];" : "=f"(f0) : "r"(ad0));
                asm volatile("ld.shared.f32 %0, [%1];" : "=f"(f1) : "r"(ad0 + 1024u));
                asm volatile("ld.shared.f32 %0, [%1];" : "=f"(f2) : "r"(ad2));
                asm volatile("ld.shared.f32 %0, [%1];" : "=f"(f3) : "r"(ad2 + 1024u));
                a[mt][0] = to_tf32(f0);
                a[mt][1] = to_tf32(f1);
                a[mt][2] = to_tf32(f2);
                a[mt][3] = to_tf32(f3);
            }

            const float4* cbuf = bf[kk & 1];
#pragma unroll
            for (int mt = 0; mt < 4; mt++)
#pragma unroll
                for (int nt = 0; nt < 8; nt++) {
                    const float4 q = cbuf[nt >> 1];
                    uint32_t b0, b1;
                    if (nt & 1) { b0 = __float_as_uint(q.z); b1 = __float_as_uint(q.w); }
                    else        { b0 = __float_as_uint(q.x); b1 = __float_as_uint(q.y); }
                    asm volatile(
                        "mma.sync.aligned.m16n8k8.row.col.f32.tf32.tf32.f32 "
                        "{%0,%1,%2,%3}, {%4,%5,%6,%7}, {%8,%9}, {%0,%1,%2,%3};"
                        : "+f"(acc[mt][nt][0]), "+f"(acc[mt][nt][1]),
                          "+f"(acc[mt][nt][2]), "+f"(acc[mt][nt][3])
                        : "r"(a[mt][0]), "r"(a[mt][1]), "r"(a[mt][2]), "r"(a[mt][3]),
                          "r"(b0), "r"(b1));
                }
        }
    }

    // ---- epilogue: bias + relu + float2 stores ----
#pragma unroll
    for (int mt = 0; mt < 4; mt++) {
        int pix = mb * 128 + wm * 64 + mt * 16 + (l >> 2);
        float* o = out + ((size_t)b * 4096 + pix) * FOUT;
#pragma unroll
        for (int nt = 0; nt < 8; nt++) {
            int f0 = wn * 64 + nt * 8 + (l & 3) * 2;
            float m0v = sMB[f0], m1v = sMB[f0 + 1];
            float2 r0, r1;
            r0.x = fmaxf(acc[mt][nt][0] + m0v, 0.f);
            r0.y = fmaxf(acc[mt][nt][1] + m1v, 0.f);
            r1.x = fmaxf(acc[mt][nt][2] + m0v, 0.f);
            r1.y = fmaxf(acc[mt][nt][3] + m1v, 0.f);
            *(float2*)(o + f0) = r0;
            *(float2*)(o + (size_t)8 * FOUT + f0) = r1;
        }
    }
}

// ============================================================================
// kernel_launch — robust input resolution:
//   1) match in_sizes as ELEMENT counts, 2) match as BYTE counts,
//   3) positional fallback in metadata order (X, W, bias, Werr, Berr).
// ============================================================================
extern "C" void kernel_launch(void* const* d_in, const int* in_sizes, int n_in,
                              void* d_out, int out_size) {
    const long long EX = 33554432LL;  // 32*64*64*128
    const long long EW = 294912LL;    // 3*3*128*256
    const long long EBI = 256LL;
    const long long EWE = 9437184LL;  // 32*9*128*256
    const long long EBE = 8192LL;     // 32*256

    const float *X = nullptr, *W = nullptr, *bias = nullptr,
                *Werr = nullptr, *Berr = nullptr;

    auto pick = [&](long long elems) -> const float* {
        for (int i = 0; i < n_in; i++) {
            long long s = (long long)in_sizes[i];
            if (s == elems || s == elems * 4) return (const float*)d_in[i];
        }
        return nullptr;
    };
    X    = pick(EX);
    W    = pick(EW);
    bias = pick(EBI);
    Werr = pick(EWE);
    Berr = pick(EBE);

    if (!X || !W || !bias || !Werr || !Berr) {
        // Positional fallback: metadata.txt order == setup_inputs dict order.
        if (n_in >= 5) {
            X    = (const float*)d_in[0];
            W    = (const float*)d_in[1];
            bias = (const float*)d_in[2];
            Werr = (const float*)d_in[3];
            Berr = (const float*)d_in[4];
        } else {
            return;  // cannot resolve inputs; avoid faulting
        }
    }

    float* out = (float*)d_out;

    prep_wfrag<<<BATCH * 9, 256>>>(W, Werr);
    conv_main<<<BATCH * 32, 256>>>(X, bias, Berr, out);
}